// round 13
// baseline (speedup 1.0000x reference)
#include <cuda_runtime.h>
#include <cstdint>

#define NB   512
#define CCH  32
#define LL   1024
#define ASTR (CCH*LL)            // 32768 floats between consecutive n rows
#define BN_EPS 1e-5f

// ---- GEMM tiling: CTA 128(n) x 128(m), 4 warps (2x2), warp tile 64x64 ----
#define BK        16
#define NSTAGE    4
#define ROWPAD    20                         // floats per smem row (conflict-free)
#define STG_BYTES (128*ROWPAD*4)             // 10240 per operand per stage
#define B_BASE_BYTES (NSTAGE*STG_BYTES)      // 40960
#define SMEM_BYTES (2*NSTAGE*STG_BYTES)      // 81920

// Scratch (allocation-free per harness rules)
__device__ float g_h1[NB*CCH*LL];
__device__ float g_h2[NB*CCH*LL];
__device__ float g_scale[CCH*LL];
__device__ float g_shift[CCH*LL];

// ---------------------------------------------------------------------------
// helpers
// ---------------------------------------------------------------------------
__device__ __forceinline__ uint32_t smem_u32(const void* p) {
    uint32_t a;
    asm("{ .reg .u64 t; cvta.to.shared.u64 t, %1; cvt.u32.u64 %0, t; }"
        : "=r"(a) : "l"(p));
    return a;
}
__device__ __forceinline__ uint32_t f2tf32(float f) {
    uint32_t u;
    asm volatile("cvt.rna.tf32.f32 %0, %1;" : "=r"(u) : "f"(f));
    return u;
}
__device__ __forceinline__ uint32_t cvtbits(uint32_t u) {
    return f2tf32(__uint_as_float(u));
}
__device__ __forceinline__ void cp16(uint32_t s, const float* g) {
    asm volatile("cp.async.ca.shared.global [%0], [%1], 16;" :: "r"(s), "l"(g));
}
__device__ __forceinline__ void ldsm4(uint32_t* r, uint32_t addr) {
    asm volatile("ldmatrix.sync.aligned.m8n8.x4.shared.b16 {%0,%1,%2,%3}, [%4];"
                 : "=r"(r[0]), "=r"(r[1]), "=r"(r[2]), "=r"(r[3]) : "r"(addr));
}
__device__ __forceinline__ void mma_tf32(float* d, const uint32_t* a,
                                         const uint32_t b0, const uint32_t b1) {
    asm volatile(
        "mma.sync.aligned.m16n8k8.row.col.f32.tf32.tf32.f32 "
        "{%0,%1,%2,%3}, {%4,%5,%6,%7}, {%8,%9}, {%0,%1,%2,%3};"
        : "+f"(d[0]), "+f"(d[1]), "+f"(d[2]), "+f"(d[3])
        : "r"(a[0]), "r"(a[1]), "r"(a[2]), "r"(a[3]), "r"(b0), "r"(b1));
}

// ---------------------------------------------------------------------------
// GEMM: out[n, c, m] = act( sum_k f(A[n,c,k]) * W[c,layer,m,k] + bias )
// MODE 0: f(a) = tf32(a)                       (layer 0, raw x)
// MODE 1: f(a) = tf32(a*scale[c,k]+shift[c,k]) (layers 1,2: fused BatchNorm)
// 128 threads: warps 2(M-n) x 2(N-m), warp tile 64x64, frags via ldmatrix.x4.
// ---------------------------------------------------------------------------
template <bool RELU, int MODE>
__global__ __launch_bounds__(128, 2)
void gemm_lm(const float* __restrict__ A, const float* __restrict__ W,
             const float* __restrict__ bias, float* __restrict__ out, int layer)
{
    extern __shared__ float smem[];
    const uint32_t sbase = smem_u32(smem);

    const int tid  = threadIdx.x;
    const int warp = tid >> 5, lane = tid & 31;
    const int g    = lane >> 2, tg = lane & 3;
    const int wm   = warp >> 1, wn = warp & 1;
    const int bx = blockIdx.x, by = blockIdx.y, c = blockIdx.z;

    const float* Ab = A + (long)(bx * 128) * ASTR + c * LL;
    const float* Wb = W + ((long)(c * 3 + layer) * LL + by * 128) * LL;

    // global->shared map: 512 float4 per operand per stage, 4 per thread
    // i = tid + 128*t : row = i>>2 (0..127), q = (i&3)*4  (bijective)
    uint32_t so[4];
    const float* ag[4];
    const float* bg[4];
#pragma unroll
    for (int t = 0; t < 4; t++) {
        const int i = tid + 128 * t;
        const int r = i >> 2, q = (i & 3) * 4;
        so[t] = (uint32_t)(r * ROWPAD + q) * 4;
        ag[t] = Ab + (long)r * ASTR + q;
        bg[t] = Wb + (long)r * LL   + q;
    }

    auto load_stage = [&](int st, int k0) {
        const uint32_t ab = sbase + (uint32_t)st * STG_BYTES;
        const uint32_t bb = ab + B_BASE_BYTES;
#pragma unroll
        for (int t = 0; t < 4; t++) cp16(ab + so[t], ag[t] + k0);
#pragma unroll
        for (int t = 0; t < 4; t++) cp16(bb + so[t], bg[t] + k0);
        asm volatile("cp.async.commit_group;");
    };

    // ldmatrix per-thread address: row = base + (lane&15), kcol = 4*(lane>>4)
    // Produces the standard m16n8k8 fragment layout:
    //   a0=A[g][tg] a1=A[g+8][tg] a2=A[g][tg+4] a3=A[g+8][tg+4]  (k rel. to ks)
    const uint32_t lrow = lane & 15, lk4 = (lane >> 4) * 4;
    const uint32_t aoff = ((uint32_t)(wm * 64 + lrow) * ROWPAD + lk4) * 4;
    const uint32_t boff = ((uint32_t)(wn * 64 + lrow) * ROWPAD + lk4) * 4;

    // fused-BN scale/shift source (k = column of A = feature of prev layer)
    const float* scp = g_scale + c * LL + tg;
    const float* shp = g_shift + c * LL + tg;

    float acc[4][8][4];
#pragma unroll
    for (int i = 0; i < 4; i++)
#pragma unroll
        for (int j = 0; j < 8; j++)
#pragma unroll
            for (int r = 0; r < 4; r++) acc[i][j][r] = 0.f;

    load_stage(0, 0);
    load_stage(1, BK);
    load_stage(2, 2 * BK);

    const int NT = LL / BK;   // 64
#pragma unroll 1
    for (int kt = 0; kt < NT; ++kt) {
        // per-ktile BN params: k offsets tg, tg+4, tg+8, tg+12
        float scv[4], shv[4];
        if (MODE == 1) {
            const int kb = kt * BK;
#pragma unroll
            for (int u = 0; u < 4; u++) {
                scv[u] = __ldg(scp + kb + 4 * u);
                shv[u] = __ldg(shp + kb + 4 * u);
            }
        }

        if (kt <= NT - 3)      asm volatile("cp.async.wait_group 2;");
        else if (kt == NT - 2) asm volatile("cp.async.wait_group 1;");
        else                   asm volatile("cp.async.wait_group 0;");
        __syncthreads();

        if (kt + 3 < NT) load_stage((kt + 3) & 3, (kt + 3) * BK);

        const uint32_t ab = sbase + (uint32_t)(kt & 3) * STG_BYTES;
        const uint32_t bb = ab + B_BASE_BYTES;

#pragma unroll
        for (int ks = 0; ks < BK; ks += 8) {
            const int u = ks >> 2;   // 0 or 2: scv index for k = ks+tg
            uint32_t af[4][4];
#pragma unroll
            for (int fm = 0; fm < 4; fm++) {
                ldsm4(af[fm], ab + aoff + (uint32_t)(fm * 16 * ROWPAD + ks) * 4);
                if (MODE == 0) {
#pragma unroll
                    for (int r = 0; r < 4; r++) af[fm][r] = cvtbits(af[fm][r]);
                } else {
                    af[fm][0] = f2tf32(fmaf(__uint_as_float(af[fm][0]), scv[u],     shv[u]));
                    af[fm][1] = f2tf32(fmaf(__uint_as_float(af[fm][1]), scv[u],     shv[u]));
                    af[fm][2] = f2tf32(fmaf(__uint_as_float(af[fm][2]), scv[u + 1], shv[u + 1]));
                    af[fm][3] = f2tf32(fmaf(__uint_as_float(af[fm][3]), scv[u + 1], shv[u + 1]));
                }
            }
            // B: 4 ldsm4 -> 8 fn frags; bm[j] = {fn(2j).b0, fn(2j+1).b0, fn(2j).b1, fn(2j+1).b1}
            uint32_t bm[4][4];
#pragma unroll
            for (int j = 0; j < 4; j++) {
                ldsm4(bm[j], bb + boff + (uint32_t)(j * 16 * ROWPAD + ks) * 4);
#pragma unroll
                for (int r = 0; r < 4; r++) bm[j][r] = cvtbits(bm[j][r]);
            }
#pragma unroll
            for (int fm = 0; fm < 4; fm++)
#pragma unroll
                for (int j = 0; j < 4; j++) {
                    mma_tf32(acc[fm][2 * j],     af[fm], bm[j][0], bm[j][2]);
                    mma_tf32(acc[fm][2 * j + 1], af[fm], bm[j][1], bm[j][3]);
                }
        }
    }

    // Epilogue: bias (+ReLU), raw fp32 float2 stores into (N, C, L)
    const float* bp = bias + (long)(c * 3 + layer) * LL + by * 128;
#pragma unroll
    for (int fm = 0; fm < 4; fm++) {
        const int n0 = bx * 128 + wm * 64 + fm * 16 + g;
#pragma unroll
        for (int fn = 0; fn < 8; fn++) {
            const int ml = wn * 64 + fn * 8 + 2 * tg;
            const int mg = by * 128 + ml;
            const float b0 = bp[ml], b1 = bp[ml + 1];
            float v0 = acc[fm][fn][0] + b0;
            float v1 = acc[fm][fn][1] + b1;
            float v2 = acc[fm][fn][2] + b0;
            float v3 = acc[fm][fn][3] + b1;
            if (RELU) {
                v0 = fmaxf(v0, 0.f); v1 = fmaxf(v1, 0.f);
                v2 = fmaxf(v2, 0.f); v3 = fmaxf(v3, 0.f);
            }
            const long o = (long)n0 * ASTR + c * LL + mg;
            *reinterpret_cast<float2*>(out + o)             = make_float2(v0, v1);
            *reinterpret_cast<float2*>(out + o + 8L * ASTR) = make_float2(v2, v3);
        }
    }
}

// ---------------------------------------------------------------------------
// BN stats: per (c, m) mean/biased-var over n -> scale/shift.
// grid (8, 32) x 512 threads: 4 n-quarters per column, smem combine.
// ---------------------------------------------------------------------------
__global__ __launch_bounds__(512)
void bn_stats(const float* __restrict__ h, const float* __restrict__ gamma,
              const float* __restrict__ beta, int j)
{
    __shared__ float ss[4][128], sq2[4][128];
    const int m_off = threadIdx.x & 127;
    const int q     = threadIdx.x >> 7;
    const int c     = blockIdx.y;
    const int m     = blockIdx.x * 128 + m_off;
    const float* p  = h + (long)c * LL + m + (long)(q * 128) * ASTR;

    float s = 0.f, sq = 0.f;
#pragma unroll 8
    for (int n = 0; n < 128; n++) {
        const float v = p[(long)n * ASTR];
        s += v; sq += v * v;
    }
    ss[q][m_off] = s; sq2[q][m_off] = sq;
    __syncthreads();
    if (q == 0) {
        s  = ss[0][m_off] + ss[1][m_off] + ss[2][m_off] + ss[3][m_off];
        sq = sq2[0][m_off] + sq2[1][m_off] + sq2[2][m_off] + sq2[3][m_off];
        const float mean = s * (1.f / NB);
        const float var  = sq * (1.f / NB) - mean * mean;    // biased
        const long  go   = (long)(c * 2 + j) * LL + m;
        const float sc   = gamma[go] * rsqrtf(var + BN_EPS);
        g_scale[c * LL + m] = sc;
        g_shift[c * LL + m] = beta[go] - mean * sc;
    }
}

// ---------------------------------------------------------------------------
extern "C" void kernel_launch(void* const* d_in, const int* in_sizes, int n_in,
                              void* d_out, int out_size)
{
    const float* x     = (const float*)d_in[0];
    const float* W     = (const float*)d_in[1];
    const float* b     = (const float*)d_in[2];
    const float* gamma = (const float*)d_in[3];
    const float* beta  = (const float*)d_in[4];
    float* out = (float*)d_out;

    float *h1 = nullptr, *h2 = nullptr;
    cudaGetSymbolAddress((void**)&h1, g_h1);
    cudaGetSymbolAddress((void**)&h2, g_h2);

    cudaFuncSetAttribute(gemm_lm<true,  0>, cudaFuncAttributeMaxDynamicSharedMemorySize, SMEM_BYTES);
    cudaFuncSetAttribute(gemm_lm<true,  1>, cudaFuncAttributeMaxDynamicSharedMemorySize, SMEM_BYTES);
    cudaFuncSetAttribute(gemm_lm<false, 1>, cudaFuncAttributeMaxDynamicSharedMemorySize, SMEM_BYTES);

    const dim3 ggrid(4, 8, 32), gblk(128);
    const dim3 sgrid(8, 32), sblk(512);

    gemm_lm<true,  0><<<ggrid, gblk, SMEM_BYTES>>>(x,  W, b, h1,  0);
    bn_stats<<<sgrid, sblk>>>(h1, gamma, beta, 0);
    gemm_lm<true,  1><<<ggrid, gblk, SMEM_BYTES>>>(h1, W, b, h2,  1);
    bn_stats<<<sgrid, sblk>>>(h2, gamma, beta, 1);
    gemm_lm<false, 1><<<ggrid, gblk, SMEM_BYTES>>>(h2, W, b, out, 2);
}